// round 2
// baseline (speedup 1.0000x reference)
#include <cuda_runtime.h>
#include <cuda_bf16.h>

#define Q_   512
#define G_   8
#define L_   6
#define HID_ 4000
#define QG_  64           // Q/G
#define INSZ_ 76          // QG + 2L
#define LEAK_ 0.6f
#define STEPS_ 400
#define EPS_ 32
#define NHIST_ 64

// Double-buffered hidden state. 2*8*4000*4 = 256 KB of __device__ scratch.
__device__ float g_h[2][G_ * HID_];

__global__ void init_h_kernel() {
    int i = blockIdx.x * blockDim.x + threadIdx.x;
    if (i < G_ * HID_) g_h[0][i] = 0.0f;
}

// One block = 16 rows of one group. smem holds h[g] (16 KB).
// One warp = one output row (dot over 4000 W_hh + 76 W_in elements).
__global__ __launch_bounds__(512) void esn_step_kernel(
    const float* __restrict__ W_in,
    const float* __restrict__ W_hh,
    const float* __restrict__ u,   // length-512 input vector for this step
    int p)                         // read g_h[p], write g_h[1-p]
{
    __shared__ float sh[HID_];

    const int rows_per_block  = 16;
    const int blocks_per_group = HID_ / rows_per_block;   // 250
    const int g    = blockIdx.x / blocks_per_group;
    const int row  = (blockIdx.x % blocks_per_group) * rows_per_block + (threadIdx.x >> 5);
    const int lane = threadIdx.x & 31;

    const float* __restrict__ hr = g_h[p] + g * HID_;
    for (int i = threadIdx.x; i < HID_; i += blockDim.x) sh[i] = hr[i];
    __syncthreads();

    // ---- W_hh @ h : float4, fully coalesced ----
    const float4* __restrict__ W4  = (const float4*)(W_hh + ((size_t)g * HID_ + row) * HID_);
    const float4* __restrict__ sh4 = (const float4*)sh;

    float acc = 0.0f;
#pragma unroll 4
    for (int k = lane; k < HID_ / 4; k += 32) {
        float4 w  = W4[k];
        float4 h4 = sh4[k];
        acc += w.x * h4.x + w.y * h4.y + w.z * h4.z + w.w * h4.w;
    }

    // ---- W_in @ u[idx] : periodic gather, 76 elems ----
    const float* __restrict__ Wi = W_in + ((size_t)g * HID_ + row) * INSZ_;
    for (int i = lane; i < INSZ_; i += 32) {
        int idx = (g * QG_ - L_ + i + Q_) & (Q_ - 1);   // Q=512 pow2, min offset -6
        acc += Wi[i] * u[idx];
    }

    // warp reduction
#pragma unroll
    for (int o = 16; o; o >>= 1) acc += __shfl_xor_sync(0xffffffffu, acc, o);

    if (lane == 0) {
        float hold = sh[row];
        g_h[1 - p][g * HID_ + row] = (1.0f - LEAK_) * hold + LEAK_ * tanhf(acc);
    }
}

// One warp per output q (512 outputs). feat = [h, h*h], length 8000.
__global__ __launch_bounds__(256) void readout_kernel(
    const float* __restrict__ W_out,
    int p,                         // g_h[p] holds the just-updated state
    float* __restrict__ y)         // 512 floats
{
    const int q    = blockIdx.x * 8 + (threadIdx.x >> 5);
    const int lane = threadIdx.x & 31;
    const int g = q / QG_;
    const int o = q % QG_;

    const float*  __restrict__ h  = g_h[p] + g * HID_;
    const float4* __restrict__ h4 = (const float4*)h;
    const float4* __restrict__ W4 = (const float4*)(W_out + ((size_t)g * QG_ + o) * 2 * HID_);

    float acc = 0.0f;
#pragma unroll 4
    for (int k = lane; k < HID_ / 4; k += 32) {
        float4 w  = W4[k];
        float4 hv = h4[k];
        acc += w.x * hv.x + w.y * hv.y + w.z * hv.z + w.w * hv.w;
    }
#pragma unroll 4
    for (int k = lane; k < HID_ / 4; k += 32) {
        float4 w  = W4[HID_ / 4 + k];
        float4 hv = h4[k];
        acc += w.x * hv.x * hv.x + w.y * hv.y * hv.y
             + w.z * hv.z * hv.z + w.w * hv.w * hv.w;
    }
#pragma unroll
    for (int ofs = 16; ofs; ofs >>= 1) acc += __shfl_xor_sync(0xffffffffu, acc, ofs);

    if (lane == 0) y[q] = acc;
}

extern "C" void kernel_launch(void* const* d_in, const int* in_sizes, int n_in,
                              void* d_out, int out_size)
{
    const float* u_hist = (const float*)d_in[0];   // [64, 512]
    const float* W_in   = (const float*)d_in[1];   // [8, 4000, 76]
    const float* W_hh   = (const float*)d_in[2];   // [8, 4000, 4000]
    const float* W_out  = (const float*)d_in[3];   // [8, 64, 8000]
    float* out = (float*)d_out;                    // [400, 512]

    (void)in_sizes; (void)n_in; (void)out_size;

    init_h_kernel<<<(G_ * HID_ + 255) / 256, 256>>>();

    const int step_grid = (HID_ / 16) * G_;        // 2000 blocks

    int p = 0;
    // Warmup on the last EPS_ history rows
    for (int t = 0; t < EPS_; t++) {
        const float* u = u_hist + (size_t)(NHIST_ - EPS_ + t) * Q_;
        esn_step_kernel<<<step_grid, 512>>>(W_in, W_hh, u, p);
        p ^= 1;
    }

    // Closed loop: u starts at u_hist[-1], then feeds back the readout
    const float* u = u_hist + (size_t)(NHIST_ - 1) * Q_;
    for (int s = 0; s < STEPS_; s++) {
        esn_step_kernel<<<step_grid, 512>>>(W_in, W_hh, u, p);
        p ^= 1;                                    // new state now in g_h[p]
        readout_kernel<<<Q_ / 8, 256>>>(W_out, p, out + (size_t)s * Q_);
        u = out + (size_t)s * Q_;
    }
}

// round 10
// speedup vs baseline: 1.6287x; 1.6287x over previous
#include <cuda_runtime.h>
#include <cuda_fp16.h>

#define Q_   512
#define G_   8
#define L_   6
#define HID_ 4000
#define QG_  64           // Q/G
#define INSZ_ 76          // QG + 2L
#define LEAK_ 0.6f
#define STEPS_ 400
#define EPS_ 32
#define NHIST_ 64
#define NROWS_ (G_ * HID_)   // 32000

// Hidden state double buffer (256 KB), int16 W_hh copy (256 MB), per-row scales.
__device__ float g_h[2][NROWS_];
__device__ short g_whh_q[(size_t)NROWS_ * HID_];
__device__ float g_scale[NROWS_];

__global__ void init_h_kernel() {
    int i = blockIdx.x * blockDim.x + threadIdx.x;
    if (i < NROWS_) g_h[0][i] = 0.0f;
}

// Per-row symmetric int16 quantization of W_hh. One block per row (32000 blocks).
// Pass 1: row max |w|; pass 2: quantize (row is 16 KB -> L1-resident for pass 2).
__global__ __launch_bounds__(256) void quant_whh_kernel(const float* __restrict__ W_hh) {
    const int r = blockIdx.x;                        // 0..31999
    const float4* __restrict__ w4 = (const float4*)(W_hh + (size_t)r * HID_);
    const int tid  = threadIdx.x;
    const int lane = tid & 31;
    const int wid  = tid >> 5;

    __shared__ float swmax[8];

    float m = 0.0f;
    for (int i = tid; i < HID_ / 4; i += 256) {      // 1000 float4
        float4 v = w4[i];
        m = fmaxf(m, fmaxf(fmaxf(fabsf(v.x), fabsf(v.y)),
                           fmaxf(fabsf(v.z), fabsf(v.w))));
    }
#pragma unroll
    for (int o = 16; o; o >>= 1) m = fmaxf(m, __shfl_xor_sync(0xffffffffu, m, o));
    if (lane == 0) swmax[wid] = m;
    __syncthreads();
    if (tid == 0) {
        float mm = swmax[0];
#pragma unroll
        for (int i = 1; i < 8; i++) mm = fmaxf(mm, swmax[i]);
        swmax[0] = fmaxf(mm, 1e-30f);
    }
    __syncthreads();
    const float rowmax = swmax[0];
    const float inv    = 32767.0f / rowmax;
    if (tid == 0) g_scale[r] = rowmax / 32767.0f;

    short4* __restrict__ q4 = (short4*)(g_whh_q + (size_t)r * HID_);
    for (int i = tid; i < HID_ / 4; i += 256) {
        float4 v = w4[i];
        short4 o;
        o.x = (short)__float2int_rn(v.x * inv);
        o.y = (short)__float2int_rn(v.y * inv);
        o.z = (short)__float2int_rn(v.z * inv);
        o.w = (short)__float2int_rn(v.w * inv);
        q4[i] = o;
    }
}

// One block = 16 rows of one group. smem holds h[g] in fp32 (16 KB).
// One warp = one output row. W_hh read as int16 (8 per lane-load), fp32
// accumulate; per-row scale applied once after the dot product.
__global__ __launch_bounds__(512) void esn_step_kernel(
    const float* __restrict__ W_in,
    const float* __restrict__ u,   // length-512 input vector for this step
    int p)                         // read g_h[p], write g_h[1-p]
{
    __shared__ float sh[HID_];

    const int rows_per_block   = 16;
    const int blocks_per_group = HID_ / rows_per_block;   // 250
    const int g    = blockIdx.x / blocks_per_group;
    const int row  = (blockIdx.x % blocks_per_group) * rows_per_block + (threadIdx.x >> 5);
    const int lane = threadIdx.x & 31;
    const int grow = g * HID_ + row;

    const float* __restrict__ hr = g_h[p] + g * HID_;
    for (int i = threadIdx.x; i < HID_; i += blockDim.x) sh[i] = hr[i];
    __syncthreads();

    // ---- W_hh @ h : int16 weights, uint4 = 8 shorts per lane, streaming ----
    const uint4* __restrict__ W = (const uint4*)(g_whh_q + (size_t)grow * HID_);
    const float4* __restrict__ sh4 = (const float4*)sh;

    float acc_hh = 0.0f;
#pragma unroll 4
    for (int k = lane; k < HID_ / 8; k += 32) {     // 500 uint4 per row
        uint4 w = __ldcs(&W[k]);
        short2 s0 = *(short2*)&w.x;
        short2 s1 = *(short2*)&w.y;
        short2 s2 = *(short2*)&w.z;
        short2 s3 = *(short2*)&w.w;
        float4 a = sh4[2 * k];
        float4 b = sh4[2 * k + 1];
        acc_hh += (float)s0.x * a.x + (float)s0.y * a.y
                + (float)s1.x * a.z + (float)s1.y * a.w;
        acc_hh += (float)s2.x * b.x + (float)s2.y * b.y
                + (float)s3.x * b.z + (float)s3.y * b.w;
    }

    // ---- W_in @ u[idx] : periodic gather, 76 elems, fp32 ----
    const float* __restrict__ Wi = W_in + (size_t)grow * INSZ_;
    float acc_in = 0.0f;
    for (int i = lane; i < INSZ_; i += 32) {
        int idx = (g * QG_ - L_ + i + Q_) & (Q_ - 1);   // Q=512 pow2, min offset -6
        acc_in += Wi[i] * u[idx];
    }

    // fold per-row scale (uniform across the warp), then one reduction
    float acc = acc_hh * g_scale[grow] + acc_in;
#pragma unroll
    for (int o = 16; o; o >>= 1) acc += __shfl_xor_sync(0xffffffffu, acc, o);

    if (lane == 0) {
        float hold = sh[row];
        g_h[1 - p][grow] = (1.0f - LEAK_) * hold + LEAK_ * tanhf(acc);
    }
}

// One warp per output q (512 outputs). feat = [h, h*h], length 8000. fp32.
__global__ __launch_bounds__(128) void readout_kernel(
    const float* __restrict__ W_out,
    int p,                         // g_h[p] holds the just-updated state
    float* __restrict__ y)         // 512 floats
{
    const int q    = blockIdx.x * 4 + (threadIdx.x >> 5);
    const int lane = threadIdx.x & 31;
    const int g = q / QG_;
    const int o = q % QG_;

    const float*  __restrict__ h  = g_h[p] + g * HID_;
    const float4* __restrict__ h4 = (const float4*)h;
    const float4* __restrict__ W4 = (const float4*)(W_out + ((size_t)g * QG_ + o) * 2 * HID_);

    float acc = 0.0f;
#pragma unroll 4
    for (int k = lane; k < HID_ / 4; k += 32) {
        float4 w  = W4[k];
        float4 hv = h4[k];
        acc += w.x * hv.x + w.y * hv.y + w.z * hv.z + w.w * hv.w;
    }
#pragma unroll 4
    for (int k = lane; k < HID_ / 4; k += 32) {
        float4 w  = W4[HID_ / 4 + k];
        float4 hv = h4[k];
        acc += w.x * hv.x * hv.x + w.y * hv.y * hv.y
             + w.z * hv.z * hv.z + w.w * hv.w * hv.w;
    }
#pragma unroll
    for (int ofs = 16; ofs; ofs >>= 1) acc += __shfl_xor_sync(0xffffffffu, acc, ofs);

    if (lane == 0) y[q] = acc;
}

extern "C" void kernel_launch(void* const* d_in, const int* in_sizes, int n_in,
                              void* d_out, int out_size)
{
    const float* u_hist = (const float*)d_in[0];   // [64, 512]
    const float* W_in   = (const float*)d_in[1];   // [8, 4000, 76]
    const float* W_hh   = (const float*)d_in[2];   // [8, 4000, 4000]
    const float* W_out  = (const float*)d_in[3];   // [8, 64, 8000]
    float* out = (float*)d_out;                    // [400, 512]

    (void)in_sizes; (void)n_in; (void)out_size;

    init_h_kernel<<<(NROWS_ + 255) / 256, 256>>>();

    // Per-row int16 quantization of W_hh (inside graph; deterministic)
    quant_whh_kernel<<<NROWS_, 256>>>(W_hh);

    const int step_grid = (HID_ / 16) * G_;        // 2000 blocks

    int p = 0;
    // Warmup on the last EPS_ history rows
    for (int t = 0; t < EPS_; t++) {
        const float* u = u_hist + (size_t)(NHIST_ - EPS_ + t) * Q_;
        esn_step_kernel<<<step_grid, 512>>>(W_in, u, p);
        p ^= 1;
    }

    // Closed loop: u starts at u_hist[-1], then feeds back the readout
    const float* u = u_hist + (size_t)(NHIST_ - 1) * Q_;
    for (int s = 0; s < STEPS_; s++) {
        esn_step_kernel<<<step_grid, 512>>>(W_in, u, p);
        p ^= 1;                                    // new state now in g_h[p]
        readout_kernel<<<Q_ / 4, 128>>>(W_out, p, out + (size_t)s * Q_);
        u = out + (size_t)s * Q_;
    }
}